// round 1
// baseline (speedup 1.0000x reference)
#include <cuda_runtime.h>
#include <math.h>

#define BB 2
#define TT 2048
#define CC 1024
#define HH 16
#define DD 64
#define C3 3072

// Scratch (allocation-free rule: __device__ globals)
__device__ float g_qkv[BB * TT * C3];  // [B,T,3C]  48 MB
__device__ float g_y[BB * TT * CC];    // [B,T,C]   16 MB

// ---------------------------------------------------------------------------
// SIMT fp32 GEMM: C[M,N] = A[M,K] @ B[K,N], row-major.
// BM=BN=128, BK=8, 256 threads, 8x8 microtile per thread.
// Per kk: 4x LDS.128 feed 64 FFMA  -> FMA-bound, not shared-bound.
// ---------------------------------------------------------------------------
__device__ __forceinline__ void gemm_body(const float* __restrict__ A,
                                          const float* __restrict__ Bm,
                                          float* __restrict__ Cm,
                                          int N, int K) {
    __shared__ float As[8][128];   // [k][m]
    __shared__ float Bs[8][128];   // [k][n]

    const int tid = threadIdx.x;
    const int tx = tid & 15;       // 0..15 -> n microtile
    const int ty = tid >> 4;       // 0..15 -> m microtile
    const int m0 = blockIdx.y * 128;
    const int n0 = blockIdx.x * 128;

    const int a_row  = tid >> 1;          // 0..127
    const int a_k4   = (tid & 1) << 2;    // 0 or 4
    const int b_krow = tid >> 5;          // 0..7
    const int b_n4   = (tid & 31) << 2;   // 0..124

    float acc[8][8];
#pragma unroll
    for (int i = 0; i < 8; i++)
#pragma unroll
        for (int j = 0; j < 8; j++) acc[i][j] = 0.f;

    const float* aptr = A + (size_t)(m0 + a_row) * K + a_k4;
    const float* bptr = Bm + (size_t)b_krow * N + n0 + b_n4;

    for (int k0 = 0; k0 < K; k0 += 8) {
        float4 av = *(const float4*)(aptr + k0);
        float4 bv = *(const float4*)(bptr + (size_t)k0 * N);
        As[a_k4 + 0][a_row] = av.x;
        As[a_k4 + 1][a_row] = av.y;
        As[a_k4 + 2][a_row] = av.z;
        As[a_k4 + 3][a_row] = av.w;
        *(float4*)&Bs[b_krow][b_n4] = bv;
        __syncthreads();

#pragma unroll
        for (int kk = 0; kk < 8; kk++) {
            float4 a0 = *(const float4*)&As[kk][ty * 8];
            float4 a1 = *(const float4*)&As[kk][ty * 8 + 4];
            float4 b0 = *(const float4*)&Bs[kk][tx * 8];
            float4 b1 = *(const float4*)&Bs[kk][tx * 8 + 4];
            float ar[8] = {a0.x, a0.y, a0.z, a0.w, a1.x, a1.y, a1.z, a1.w};
            float br[8] = {b0.x, b0.y, b0.z, b0.w, b1.x, b1.y, b1.z, b1.w};
#pragma unroll
            for (int i = 0; i < 8; i++)
#pragma unroll
                for (int j = 0; j < 8; j++)
                    acc[i][j] += ar[i] * br[j];
        }
        __syncthreads();
    }

#pragma unroll
    for (int i = 0; i < 8; i++) {
        float* crow = Cm + (size_t)(m0 + ty * 8 + i) * N + n0 + tx * 8;
        *(float4*)crow       = make_float4(acc[i][0], acc[i][1], acc[i][2], acc[i][3]);
        *(float4*)(crow + 4) = make_float4(acc[i][4], acc[i][5], acc[i][6], acc[i][7]);
    }
}

__global__ __launch_bounds__(256) void gemm_qkv_kernel(const float* __restrict__ x,
                                                       const float* __restrict__ w) {
    gemm_body(x, w, g_qkv, C3, CC);
}

__global__ __launch_bounds__(256) void gemm_proj_kernel(const float* __restrict__ w,
                                                        float* __restrict__ out) {
    gemm_body(g_y, w, out, CC, CC);
}

// ---------------------------------------------------------------------------
// Flash-style attention. One CTA per (b,h, 64-query tile). 256 threads.
// Thread (r = tid/4, cg = tid%4): owns query row r; computes S for the 16 keys
// j = cg + 4*jj (strided -> conflict-free K reads), owns O columns
// [cg*16, cg*16+16). Q row lives in registers. K and V share one smem buffer.
// Online softmax; per-row (m,l) replicated across the 4 threads of a row via
// shuffles (lanes r*4+cg are contiguous, xor 1/2 stays in the group).
// ---------------------------------------------------------------------------
__global__ __launch_bounds__(256) void attn_kernel() {
    __shared__ float KVs[64][68];  // K tile then V tile (stride 68: conflict-free)
    __shared__ float Ps[64][68];   // softmax probabilities for current tile

    const int tid = threadIdx.x;
    const int r  = tid >> 2;       // 0..63 query row in tile
    const int cg = tid & 3;        // 0..3 column group
    const int qt = blockIdx.x;     // 0..31 query tile
    const int b  = blockIdx.y >> 4;
    const int h  = blockIdx.y & 15;
    const int qrow = qt * 64 + r;

    // Q row -> registers (64 floats)
    const float* qptr = g_qkv + (size_t)(b * TT + qrow) * C3 + h * DD;
    float4 q[16];
#pragma unroll
    for (int i = 0; i < 16; i++) q[i] = *(const float4*)(qptr + 4 * i);

    float4 o[4];
#pragma unroll
    for (int i = 0; i < 4; i++) o[i] = make_float4(0.f, 0.f, 0.f, 0.f);
    float mrow = -1e30f, lrow = 0.f;

    const int kbase = b * TT;

    for (int kt = 0; kt < TT / 64; kt++) {
        // ---- load K tile [64 x 64] ----
#pragma unroll
        for (int i = 0; i < 4; i++) {
            int f = tid + 256 * i;
            int row = f >> 4, dq = f & 15;
            *(float4*)&KVs[row][dq * 4] =
                *(const float4*)(g_qkv + (size_t)(kbase + kt * 64 + row) * C3 + CC + h * DD + dq * 4);
        }
        __syncthreads();

        // ---- S = Q K^T * scale for 16 strided keys ----
        float p[16];
        float mloc = -1e30f;
#pragma unroll
        for (int jj = 0; jj < 16; jj++) {
            const int j = cg + 4 * jj;
            float s = 0.f;
#pragma unroll
            for (int dv = 0; dv < 16; dv++) {
                float4 kv = *(const float4*)&KVs[j][dv * 4];
                s += q[dv].x * kv.x;
                s += q[dv].y * kv.y;
                s += q[dv].z * kv.z;
                s += q[dv].w * kv.w;
            }
            s *= 0.125f;  // 1/sqrt(64)
            p[jj] = s;
            mloc = fmaxf(mloc, s);
        }
        // row max / sum across the 4 threads of this row
        mloc = fmaxf(mloc, __shfl_xor_sync(0xffffffffu, mloc, 1));
        mloc = fmaxf(mloc, __shfl_xor_sync(0xffffffffu, mloc, 2));
        const float mnew  = fmaxf(mrow, mloc);
        const float alpha = __expf(mrow - mnew);
        float lsum = 0.f;
#pragma unroll
        for (int jj = 0; jj < 16; jj++) {
            float pv = __expf(p[jj] - mnew);
            p[jj] = pv;
            lsum += pv;
        }
        lsum += __shfl_xor_sync(0xffffffffu, lsum, 1);
        lsum += __shfl_xor_sync(0xffffffffu, lsum, 2);
        lrow = lrow * alpha + lsum;
        mrow = mnew;

#pragma unroll
        for (int jj = 0; jj < 16; jj++) Ps[r][cg + 4 * jj] = p[jj];
        __syncthreads();  // P visible; all K reads done -> safe to overwrite KVs

        // ---- load V tile into the same buffer ----
#pragma unroll
        for (int i = 0; i < 4; i++) {
            int f = tid + 256 * i;
            int row = f >> 4, dq = f & 15;
            *(float4*)&KVs[row][dq * 4] =
                *(const float4*)(g_qkv + (size_t)(kbase + kt * 64 + row) * C3 + 2 * CC + h * DD + dq * 4);
        }
        __syncthreads();

        // ---- O = O*alpha + P @ V ----
#pragma unroll
        for (int i = 0; i < 4; i++) {
            o[i].x *= alpha; o[i].y *= alpha; o[i].z *= alpha; o[i].w *= alpha;
        }
#pragma unroll 4
        for (int j = 0; j < 64; j++) {
            const float pv = Ps[r][j];
#pragma unroll
            for (int i = 0; i < 4; i++) {
                float4 vv = *(const float4*)&KVs[j][cg * 16 + 4 * i];
                o[i].x += pv * vv.x;
                o[i].y += pv * vv.y;
                o[i].z += pv * vv.z;
                o[i].w += pv * vv.w;
            }
        }
        __syncthreads();  // V reads done before next K load
    }

    const float inv = 1.f / lrow;
    float* yp = g_y + (size_t)(b * TT + qrow) * CC + h * DD + cg * 16;
#pragma unroll
    for (int i = 0; i < 4; i++) {
        float4 ov = o[i];
        ov.x *= inv; ov.y *= inv; ov.z *= inv; ov.w *= inv;
        *(float4*)(yp + 4 * i) = ov;
    }
}

// ---------------------------------------------------------------------------
extern "C" void kernel_launch(void* const* d_in, const int* in_sizes, int n_in,
                              void* d_out, int out_size) {
    const float* x      = (const float*)d_in[0];   // [B,T,C]
    const float* w_attn = (const float*)d_in[1];   // [C,3C]
    const float* w_proj = (const float*)d_in[2];   // [C,C]
    float* out = (float*)d_out;                    // [B,T,C]

    gemm_qkv_kernel<<<dim3(C3 / 128, (BB * TT) / 128), 256>>>(x, w_attn);
    attn_kernel<<<dim3(TT / 64, BB * HH), 256>>>();
    gemm_proj_kernel<<<dim3(CC / 128, (BB * TT) / 128), 256>>>(w_proj, out);
}